// round 4
// baseline (speedup 1.0000x reference)
#include <cuda_runtime.h>
#include <cuda_bf16.h>
#include <cstdint>
#include <cstddef>

// ============================================================
// Problem constants
// ============================================================
#define TOKENS 32768
#define HIDDEN 2048
#define EPSV   1e-6f

// GEMM tiling (shared by both compute paths)
constexpr int TM  = 128;            // CTA M tile
constexpr int TN  = 256;            // CTA N tile
constexpr int TK  = 64;             // K chunk (bf16 -> 128 bytes/row = SW128 atom)
constexpr int KCH = HIDDEN / TK;    // 32 chunks

constexpr int ST_A = TM * 128;          // 16384 B per A subtile (hi or lo)
constexpr int ST_B = TN * 128;          // 32768 B per B subtile
constexpr int STAGE_BYTES = 2 * ST_A + 2 * ST_B;   // 98304
constexpr int SMEM_TILES  = 1024;
constexpr int SMEM_TOTAL  = SMEM_TILES + 2 * STAGE_BYTES;  // 197632

// Feature gate: tcgen05 only exists when the virtual arch is the 'a' variant.
#if defined(__CUDA_ARCH_FEAT_SM103_ALL) || defined(__CUDA_ARCH_FEAT_SM100_ALL)
#define USE_TCGEN05 1
#else
#define USE_TCGEN05 0
#endif

// idesc for tcgen05.mma cta_group::1 kind::f16, bf16 x bf16 -> f32
constexpr uint32_t IDESC =
    (1u << 4) | (1u << 7) | (1u << 10) | ((TN / 8) << 17) | ((TM / 16) << 24);

// ============================================================
// Device scratch (no allocation allowed)
// ============================================================
__device__ float          g_resid[(size_t)TOKENS * HIDDEN];
__device__ __nv_bfloat16  g_yhi  [(size_t)TOKENS * HIDDEN];
__device__ __nv_bfloat16  g_ylo  [(size_t)TOKENS * HIDDEN];
__device__ __nv_bfloat16  g_whiT [3][(size_t)HIDDEN * HIDDEN];
__device__ __nv_bfloat16  g_wloT [3][(size_t)HIDDEN * HIDDEN];

// ============================================================
// Helpers
// ============================================================
__device__ __forceinline__ uint32_t smem_u32(const void* p) {
    uint32_t a;
    asm("{ .reg .u64 t; cvta.to.shared.u64 t, %1; cvt.u32.u64 %0, t; }" : "=r"(a) : "l"(p));
    return a;
}

#define SW128(o) ((o) ^ (((o) >> 3) & 0x70))

#define CP_ASYNC16(dst, src) \
    asm volatile("cp.async.cg.shared.global [%0], [%1], 16;\n" :: "r"(dst), "l"(src))
#define CP_COMMIT() asm volatile("cp.async.commit_group;\n" ::: "memory")
#define CP_WAIT1()  asm volatile("cp.async.wait_group 1;\n" ::: "memory")
#define CP_WAIT0()  asm volatile("cp.async.wait_group 0;\n" ::: "memory")

#if USE_TCGEN05
__device__ __forceinline__ uint32_t elect_one() {
    uint32_t pred;
    asm volatile("{ .reg .pred p; elect.sync _|p, 0xFFFFFFFF; selp.b32 %0, 1, 0, p; }" : "=r"(pred));
    return pred;
}

#define MBARRIER_INIT(addr, cnt) \
    asm volatile("mbarrier.init.shared.b64 [%0], %1;" :: "r"((uint32_t)(addr)), "r"((uint32_t)(cnt)) : "memory")
#define MBARRIER_INVAL(addr) \
    asm volatile("mbarrier.inval.shared.b64 [%0];" :: "r"((uint32_t)(addr)) : "memory")

#define MBARRIER_WAIT_PARITY(mbar_smem_addr, phase_parity) do { \
    uint32_t _mbar = (uint32_t)(mbar_smem_addr); \
    uint32_t _parity = (uint32_t)(phase_parity); \
    uint32_t _done; \
    asm volatile( \
        "{\n\t.reg .pred p;\n\t" \
        "mbarrier.try_wait.parity.acquire.cta.shared::cta.b64 p, [%1], %2;\n\t" \
        "selp.b32 %0, 1, 0, p;\n\t}" \
        : "=r"(_done) : "r"(_mbar), "r"(_parity) : "memory"); \
    if (!_done) { \
        asm volatile( \
            "{\n\t.reg .pred P1;\n\t" \
            "WAIT_LOOP_%=:\n\t" \
            "mbarrier.try_wait.parity.acquire.cta.shared::cta.b64 P1, [%0], %1, 0x989680;\n\t" \
            "@P1 bra.uni WAIT_DONE_%=;\n\t" \
            "bra.uni WAIT_LOOP_%=;\n\t" \
            "WAIT_DONE_%=:\n\t}" \
            :: "r"(_mbar), "r"(_parity) : "memory"); \
    } \
} while(0)

#define TCGEN05_ALLOC(smem_result_addr, nCols) \
    asm volatile("tcgen05.alloc.cta_group::1.sync.aligned.shared::cta.b32 [%0], %1;" \
        :: "r"((uint32_t)(smem_result_addr)), "r"((uint32_t)(nCols)) : "memory")
#define TCGEN05_DEALLOC(tmem_addr, nCols) \
    asm volatile("tcgen05.dealloc.cta_group::1.sync.aligned.b32 %0, %1;" :: "r"(tmem_addr), "r"(nCols))
#define TCGEN05_RELINQUISH() \
    asm volatile("tcgen05.relinquish_alloc_permit.cta_group::1.sync.aligned;")
#define TCGEN05_COMMIT(mbar) \
    asm volatile("tcgen05.commit.cta_group::1.mbarrier::arrive::one.shared::cluster.b64 [%0];" \
        :: "r"((uint32_t)(mbar)) : "memory")
#define TCGEN05_WAIT_LD() asm volatile("tcgen05.wait::ld.sync.aligned;" ::: "memory")
#define TCGEN05_FENCE_BEFORE() asm volatile("tcgen05.fence::before_thread_sync;" ::: "memory")
#define TCGEN05_FENCE_AFTER()  asm volatile("tcgen05.fence::after_thread_sync;" ::: "memory")

#define TCGEN05_LD_32X32B_X32(r, tmem_addr) \
    asm volatile( \
        "tcgen05.ld.sync.aligned.32x32b.x32.b32 " \
        "{%0, %1, %2, %3, %4, %5, %6, %7, " \
        " %8, %9, %10, %11, %12, %13, %14, %15, " \
        " %16, %17, %18, %19, %20, %21, %22, %23, " \
        " %24, %25, %26, %27, %28, %29, %30, %31}, [%32];" \
        : "=r"((r)[0]),  "=r"((r)[1]),  "=r"((r)[2]),  "=r"((r)[3]), \
          "=r"((r)[4]),  "=r"((r)[5]),  "=r"((r)[6]),  "=r"((r)[7]), \
          "=r"((r)[8]),  "=r"((r)[9]),  "=r"((r)[10]), "=r"((r)[11]), \
          "=r"((r)[12]), "=r"((r)[13]), "=r"((r)[14]), "=r"((r)[15]), \
          "=r"((r)[16]), "=r"((r)[17]), "=r"((r)[18]), "=r"((r)[19]), \
          "=r"((r)[20]), "=r"((r)[21]), "=r"((r)[22]), "=r"((r)[23]), \
          "=r"((r)[24]), "=r"((r)[25]), "=r"((r)[26]), "=r"((r)[27]), \
          "=r"((r)[28]), "=r"((r)[29]), "=r"((r)[30]), "=r"((r)[31]) \
        : "r"(tmem_addr))

static constexpr uint64_t SMEM_DESC_BASE_SW128 =
    (uint64_t(2)  << 61) | (uint64_t(1) << 46) | (uint64_t(64) << 32) | (uint64_t(1) << 16);
#define MAKE_SMEM_DESC(base_addr) \
    (SMEM_DESC_BASE_SW128 | ((uint64_t)((base_addr) >> 4) & 0x3FFF))

__device__ __forceinline__ void mma_f16_ss(uint32_t d_tmem, uint64_t a_desc, uint64_t b_desc,
                                           uint32_t idesc, uint32_t enable) {
    asm volatile(
        "{\n\t.reg .pred p;\n\t"
        "setp.ne.u32 p, %5, 0;\n\t"
        "tcgen05.mma.cta_group::1.kind::f16 [%0], %1, %2, %3, {%4, %4, %4, %4}, p;\n\t}"
        :: "r"(d_tmem), "l"(a_desc), "l"(b_desc), "r"(idesc), "r"(0u), "r"(enable)
        : "memory");
}
#else
// ---- legacy mma.sync path helpers (compile everywhere) ----
__device__ __forceinline__ void ldsm_x4(uint32_t addr, uint32_t& r0, uint32_t& r1,
                                        uint32_t& r2, uint32_t& r3) {
    asm volatile("ldmatrix.sync.aligned.m8n8.x4.shared.b16 {%0,%1,%2,%3}, [%4];"
        : "=r"(r0), "=r"(r1), "=r"(r2), "=r"(r3) : "r"(addr));
}
__device__ __forceinline__ void ldsm_x2(uint32_t addr, uint32_t& r0, uint32_t& r1) {
    asm volatile("ldmatrix.sync.aligned.m8n8.x2.shared.b16 {%0,%1}, [%2];"
        : "=r"(r0), "=r"(r1) : "r"(addr));
}
__device__ __forceinline__ void mma16816(float& d0, float& d1, float& d2, float& d3,
                                         uint32_t a0, uint32_t a1, uint32_t a2, uint32_t a3,
                                         uint32_t b0, uint32_t b1) {
    asm volatile(
        "mma.sync.aligned.m16n8k16.row.col.f32.bf16.bf16.f32 "
        "{%0,%1,%2,%3}, {%4,%5,%6,%7}, {%8,%9}, {%0,%1,%2,%3};"
        : "+f"(d0), "+f"(d1), "+f"(d2), "+f"(d3)
        : "r"(a0), "r"(a1), "r"(a2), "r"(a3), "r"(b0), "r"(b1));
}
#endif

// ============================================================
// Weight prep: transpose + bf16 hi/lo split.  W[k][n] -> WT[n][k]
// ============================================================
__global__ void prep_w(const float* __restrict__ W, int widx) {
    __shared__ float t[32][33];
    int x = blockIdx.x * 32 + threadIdx.x;   // n
    int y = blockIdx.y * 32 + threadIdx.y;   // k
    t[threadIdx.y][threadIdx.x] = W[(size_t)y * HIDDEN + x];
    __syncthreads();
    int n = blockIdx.x * 32 + threadIdx.y;
    int k = blockIdx.y * 32 + threadIdx.x;
    float v = t[threadIdx.x][threadIdx.y];
    __nv_bfloat16 h = __float2bfloat16(v);
    float lo = v - __bfloat162float(h);
    g_whiT[widx][(size_t)n * HIDDEN + k] = h;
    g_wloT[widx][(size_t)n * HIDDEN + k] = __float2bfloat16(lo);
}

// ============================================================
// Fused (relu) + rmsnorm.
// ============================================================
__global__ void __launch_bounds__(256) norm_kernel(const float* __restrict__ in,
                                                   const float* __restrict__ gain,
                                                   float* __restrict__ outf,
                                                   int flags) {
    int row = blockIdx.x;
    int tid = threadIdx.x;
    const float* src = in ? in : g_resid;
    const float4* inp = reinterpret_cast<const float4*>(src + (size_t)row * HIDDEN);
    float4 v0 = inp[tid];
    float4 v1 = inp[tid + 256];

    if (flags & 1) {
        v0.x = fmaxf(v0.x, 0.f); v0.y = fmaxf(v0.y, 0.f);
        v0.z = fmaxf(v0.z, 0.f); v0.w = fmaxf(v0.w, 0.f);
        v1.x = fmaxf(v1.x, 0.f); v1.y = fmaxf(v1.y, 0.f);
        v1.z = fmaxf(v1.z, 0.f); v1.w = fmaxf(v1.w, 0.f);
        float4* rr = reinterpret_cast<float4*>(g_resid + (size_t)row * HIDDEN);
        rr[tid] = v0;
        rr[tid + 256] = v1;
    }

    float ss = v0.x * v0.x + v0.y * v0.y + v0.z * v0.z + v0.w * v0.w
             + v1.x * v1.x + v1.y * v1.y + v1.z * v1.z + v1.w * v1.w;
#pragma unroll
    for (int o = 16; o; o >>= 1) ss += __shfl_xor_sync(0xFFFFFFFFu, ss, o);
    __shared__ float red[8];
    if ((tid & 31) == 0) red[tid >> 5] = ss;
    __syncthreads();
    float tot = 0.f;
#pragma unroll
    for (int i = 0; i < 8; i++) tot += red[i];
    float scale = rsqrtf(tot * (1.0f / HIDDEN) + EPSV);

    const float4* gp = reinterpret_cast<const float4*>(gain);
    float4 gv0 = gp[tid], gv1 = gp[tid + 256];
    float4 y0, y1;
    y0.x = v0.x * scale * gv0.x; y0.y = v0.y * scale * gv0.y;
    y0.z = v0.z * scale * gv0.z; y0.w = v0.w * scale * gv0.w;
    y1.x = v1.x * scale * gv1.x; y1.y = v1.y * scale * gv1.y;
    y1.z = v1.z * scale * gv1.z; y1.w = v1.w * scale * gv1.w;

    if (flags & 2) {
        __nv_bfloat16 h[8], l[8];
        float yv[8] = {y0.x, y0.y, y0.z, y0.w, y1.x, y1.y, y1.z, y1.w};
#pragma unroll
        for (int i = 0; i < 8; i++) {
            h[i] = __float2bfloat16(yv[i]);
            l[i] = __float2bfloat16(yv[i] - __bfloat162float(h[i]));
        }
        uint2* hp = reinterpret_cast<uint2*>(g_yhi + (size_t)row * HIDDEN);
        uint2* lp = reinterpret_cast<uint2*>(g_ylo + (size_t)row * HIDDEN);
        uint2 ph0, ph1, pl0, pl1;
        __nv_bfloat162 t;
        t = __nv_bfloat162(h[0], h[1]); ph0.x = *reinterpret_cast<uint32_t*>(&t);
        t = __nv_bfloat162(h[2], h[3]); ph0.y = *reinterpret_cast<uint32_t*>(&t);
        t = __nv_bfloat162(h[4], h[5]); ph1.x = *reinterpret_cast<uint32_t*>(&t);
        t = __nv_bfloat162(h[6], h[7]); ph1.y = *reinterpret_cast<uint32_t*>(&t);
        t = __nv_bfloat162(l[0], l[1]); pl0.x = *reinterpret_cast<uint32_t*>(&t);
        t = __nv_bfloat162(l[2], l[3]); pl0.y = *reinterpret_cast<uint32_t*>(&t);
        t = __nv_bfloat162(l[4], l[5]); pl1.x = *reinterpret_cast<uint32_t*>(&t);
        t = __nv_bfloat162(l[6], l[7]); pl1.y = *reinterpret_cast<uint32_t*>(&t);
        hp[tid] = ph0; hp[tid + 256] = ph1;
        lp[tid] = pl0; lp[tid + 256] = pl1;
    } else {
        float4* op = reinterpret_cast<float4*>(outf + (size_t)row * HIDDEN);
        op[tid] = y0;
        op[tid + 256] = y1;
    }
}

// ============================================================
// Shared loader: one K chunk (A hi/lo + B hi/lo) into SW128 SMEM stage.
// 256 threads.
// ============================================================
__device__ __forceinline__ void load_chunk(uint32_t sbase, int m0, int n0, int k0,
                                           const char* Bh, const char* Bl, int tid) {
    const char* Ah = reinterpret_cast<const char*>(g_yhi);
    const char* Al = reinterpret_cast<const char*>(g_ylo);
    // A: 2 tensors x 128 rows x 8 x 16B = 2048 transfers
#pragma unroll
    for (int i = tid; i < 2048; i += 256) {
        int t = i >> 10; int rem = i & 1023; int r = rem >> 3; int cb = (rem & 7) * 16;
        uint32_t dst = sbase + t * ST_A + SW128(r * 128 + cb);
        const char* src = (t ? Al : Ah) + ((size_t)(m0 + r) * HIDDEN + k0) * 2 + cb;
        CP_ASYNC16(dst, src);
    }
    // B: 2 tensors x 256 rows x 8 x 16B = 4096 transfers
#pragma unroll
    for (int i = tid; i < 4096; i += 256) {
        int t = i >> 11; int rem = i & 2047; int r = rem >> 3; int cb = (rem & 7) * 16;
        uint32_t dst = sbase + 2 * ST_A + t * ST_B + SW128(r * 128 + cb);
        const char* src = (t ? Bl : Bh) + ((size_t)(n0 + r) * HIDDEN + k0) * 2 + cb;
        CP_ASYNC16(dst, src);
    }
}

// ============================================================
// GEMM: resid[m,n] += sum_k y[m,k] * W[k,n]  (split bf16 x3)
// ============================================================
__global__ void __launch_bounds__(256, 1) __cluster_dims__(1, 1, 1)
gemm_kernel(int widx) {
    extern __shared__ char smem[];
    uint32_t sb = smem_u32(smem);
    int tid = threadIdx.x, wid = tid >> 5, lid = tid & 31;
    int n0 = blockIdx.x * TN;
    int m0 = blockIdx.y * TM;
    const char* Bhg = reinterpret_cast<const char*>(g_whiT[widx]);
    const char* Blg = reinterpret_cast<const char*>(g_wloT[widx]);

    const uint32_t stage_base[2] = { sb + SMEM_TILES, sb + SMEM_TILES + STAGE_BYTES };

#if USE_TCGEN05
    // ---------------- tcgen05 path ----------------
    if (wid == 0) TCGEN05_ALLOC(sb + 0, 256);
    if (tid == 0) {
        MBARRIER_INIT(sb + 16, 1);
        MBARRIER_INIT(sb + 24, 1);
        MBARRIER_INIT(sb + 32, 1);
    }
    __syncthreads();
    uint32_t tbase;
    asm volatile("ld.shared.b32 %0, [%1];" : "=r"(tbase) : "r"(sb + 0));

    load_chunk(stage_base[0], m0, n0, 0, Bhg, Blg, tid);
    CP_COMMIT();

    for (int c = 0; c < KCH; ++c) {
        int s = c & 1;
        if (c + 1 < KCH) {
            if (c >= 1) MBARRIER_WAIT_PARITY(sb + 16 + 8 * ((c - 1) & 1), ((c - 1) >> 1) & 1);
            load_chunk(stage_base[(c + 1) & 1], m0, n0, (c + 1) * TK, Bhg, Blg, tid);
            CP_COMMIT();
            CP_WAIT1();
        } else {
            CP_WAIT0();
        }
        asm volatile("fence.proxy.async.shared::cta;" ::: "memory");
        __syncthreads();

        if (wid == 0 && elect_one()) {
            uint64_t ah = MAKE_SMEM_DESC(stage_base[s]);
            uint64_t al = MAKE_SMEM_DESC(stage_base[s] + ST_A);
            uint64_t bh = MAKE_SMEM_DESC(stage_base[s] + 2 * ST_A);
            uint64_t bl = MAKE_SMEM_DESC(stage_base[s] + 2 * ST_A + ST_B);
#pragma unroll
            for (int ks = 0; ks < 4; ++ks) {
                mma_f16_ss(tbase, ah + ks * 2, bh + ks * 2, IDESC, (c != 0 || ks != 0));
                mma_f16_ss(tbase, ah + ks * 2, bl + ks * 2, IDESC, 1u);
                mma_f16_ss(tbase, al + ks * 2, bh + ks * 2, IDESC, 1u);
            }
            if (c == KCH - 1) TCGEN05_COMMIT(sb + 32);
            else              TCGEN05_COMMIT(sb + 16 + 8 * s);
        }
    }

    MBARRIER_WAIT_PARITY(sb + 32, 0);
    TCGEN05_FENCE_AFTER();

    // epilogue: 8 warps; warp w -> TMEM subpartition w&3 (rows (w&3)*32..+31),
    // column groups (w>>2)*4 .. +3 (each 32 fp32 cols).
    {
        int row = (wid & 3) * 32 + lid;
        float* rp = g_resid + (size_t)(m0 + row) * HIDDEN + n0;
#pragma unroll
        for (int g = 0; g < 4; ++g) {
            int gcol = (wid >> 2) * 4 + g;
            uint32_t d[32];
            TCGEN05_LD_32X32B_X32(d, tbase + gcol * 32);
            TCGEN05_WAIT_LD();
#pragma unroll
            for (int j = 0; j < 32; j += 4) {
                float4 r4 = *reinterpret_cast<float4*>(rp + gcol * 32 + j);
                r4.x += __uint_as_float(d[j + 0]);
                r4.y += __uint_as_float(d[j + 1]);
                r4.z += __uint_as_float(d[j + 2]);
                r4.w += __uint_as_float(d[j + 3]);
                *reinterpret_cast<float4*>(rp + gcol * 32 + j) = r4;
            }
        }
    }
    TCGEN05_FENCE_BEFORE();
    __syncthreads();
    if (tid == 0) { MBARRIER_INVAL(sb + 16); MBARRIER_INVAL(sb + 24); MBARRIER_INVAL(sb + 32); }
    if (wid == 0) { TCGEN05_RELINQUISH(); TCGEN05_DEALLOC(tbase, 256); }

#else
    // ---------------- legacy mma.sync fallback ----------------
    // 8 warps, warp grid 2(m) x 4(n); warp tile 64x64.
    int wm = wid & 1;          // 0..1
    int wn = wid >> 1;         // 0..3
    int wm0 = wm * 64;         // row offset in CTA tile
    int wn0 = wn * 64;         // col offset in CTA tile

    float acc[4][8][4];        // [m16 tile][n8 tile][frag]
#pragma unroll
    for (int i = 0; i < 4; i++)
#pragma unroll
        for (int j = 0; j < 8; j++)
#pragma unroll
            for (int q = 0; q < 4; q++) acc[i][j][q] = 0.f;

    load_chunk(stage_base[0], m0, n0, 0, Bhg, Blg, tid);
    CP_COMMIT();

    for (int c = 0; c < KCH; ++c) {
        int s = c & 1;
        if (c + 1 < KCH) {
            load_chunk(stage_base[(c + 1) & 1], m0, n0, (c + 1) * TK, Bhg, Blg, tid);
            CP_COMMIT();
            CP_WAIT1();
        } else {
            CP_WAIT0();
        }
        __syncthreads();

        uint32_t aBaseH = stage_base[s];
        uint32_t aBaseL = stage_base[s] + ST_A;
        uint32_t bBaseH = stage_base[s] + 2 * ST_A;
        uint32_t bBaseL = stage_base[s] + 2 * ST_A + ST_B;

#pragma unroll
        for (int ks = 0; ks < 4; ++ks) {
            int kbyte = ks * 32;   // 16 bf16 per k-step
            // A fragments: 4 m16 tiles, hi+lo
            uint32_t ah[4][4], al[4][4];
#pragma unroll
            for (int mt = 0; mt < 4; ++mt) {
                int r = wm0 + mt * 16 + (lid & 15);
                int cb = kbyte + ((lid >> 4) << 4);
                uint32_t off = SW128(r * 128 + cb);
                ldsm_x4(aBaseH + off, ah[mt][0], ah[mt][1], ah[mt][2], ah[mt][3]);
                ldsm_x4(aBaseL + off, al[mt][0], al[mt][1], al[mt][2], al[mt][3]);
            }
            // B fragments per n8 tile
#pragma unroll
            for (int nt = 0; nt < 8; ++nt) {
                int r = wn0 + nt * 8 + (lid & 7);
                int cb = kbyte + (((lid >> 3) & 1) << 4);
                uint32_t off = SW128(r * 128 + cb);
                uint32_t bh0, bh1, bl0, bl1;
                ldsm_x2(bBaseH + off, bh0, bh1);
                ldsm_x2(bBaseL + off, bl0, bl1);
#pragma unroll
                for (int mt = 0; mt < 4; ++mt) {
                    mma16816(acc[mt][nt][0], acc[mt][nt][1], acc[mt][nt][2], acc[mt][nt][3],
                             ah[mt][0], ah[mt][1], ah[mt][2], ah[mt][3], bh0, bh1);
                    mma16816(acc[mt][nt][0], acc[mt][nt][1], acc[mt][nt][2], acc[mt][nt][3],
                             ah[mt][0], ah[mt][1], ah[mt][2], ah[mt][3], bl0, bl1);
                    mma16816(acc[mt][nt][0], acc[mt][nt][1], acc[mt][nt][2], acc[mt][nt][3],
                             al[mt][0], al[mt][1], al[mt][2], al[mt][3], bh0, bh1);
                }
            }
        }
        __syncthreads();   // everyone done reading stage s before it is reloaded
    }

    // epilogue: resid += acc
    {
        int qrow = lid >> 2;          // 0..7
        int qcol = (lid & 3) * 2;     // 0,2,4,6
#pragma unroll
        for (int mt = 0; mt < 4; ++mt) {
#pragma unroll
            for (int nt = 0; nt < 8; ++nt) {
                int grow = m0 + wm0 + mt * 16 + qrow;
                int gcol = n0 + wn0 + nt * 8 + qcol;
                float* p0 = g_resid + (size_t)grow * HIDDEN + gcol;
                float2 v0 = *reinterpret_cast<float2*>(p0);
                v0.x += acc[mt][nt][0]; v0.y += acc[mt][nt][1];
                *reinterpret_cast<float2*>(p0) = v0;
                float* p1 = g_resid + (size_t)(grow + 8) * HIDDEN + gcol;
                float2 v1 = *reinterpret_cast<float2*>(p1);
                v1.x += acc[mt][nt][2]; v1.y += acc[mt][nt][3];
                *reinterpret_cast<float2*>(p1) = v1;
            }
        }
    }
#endif
}

// ============================================================
// kernel_launch
// ============================================================
extern "C" void kernel_launch(void* const* d_in, const int* in_sizes, int n_in,
                              void* d_out, int out_size) {
    const float* x  = (const float*)d_in[0];
    const float* g0 = (const float*)d_in[1];
    const float* g1 = (const float*)d_in[2];
    const float* g2 = (const float*)d_in[3];
    const float* g3 = (const float*)d_in[4];
    const float* W[3] = { (const float*)d_in[5], (const float*)d_in[6], (const float*)d_in[7] };
    const float* gains[3] = { g1, g2, g3 };
    float* out = (float*)d_out;

    cudaFuncSetAttribute(gemm_kernel, cudaFuncAttributeMaxDynamicSharedMemorySize, SMEM_TOTAL);

    dim3 pb(32, 32), pg(HIDDEN / 32, HIDDEN / 32);
    for (int i = 0; i < 3; i++) prep_w<<<pg, pb>>>(W[i], i);

    norm_kernel<<<TOKENS, 256>>>(x, g0, nullptr, /*relu|split*/ 3);

    dim3 gg(HIDDEN / TN, TOKENS / TM);  // (8, 256)
    for (int s = 0; s < 3; s++) {
        gemm_kernel<<<gg, 256, SMEM_TOTAL>>>(s);
        if (s < 2) {
            norm_kernel<<<TOKENS, 256>>>(nullptr, gains[s], nullptr, /*split*/ 2);
        } else {
            norm_kernel<<<TOKENS, 256>>>(nullptr, gains[s], out, /*fp32 out*/ 0);
        }
    }
}

// round 5
// speedup vs baseline: 1.2522x; 1.2522x over previous
#include <cuda_runtime.h>
#include <cuda_bf16.h>
#include <cuda_fp16.h>
#include <cstdint>
#include <cstddef>

// ============================================================
// Problem constants
// ============================================================
#define TOKENS 32768
#define HIDDEN 2048
#define EPSV   1e-6f

// GEMM tiling
constexpr int TM  = 128;            // CTA M tile
constexpr int TN  = 256;            // CTA N tile
constexpr int TK  = 64;             // K chunk (fp16 -> 128 bytes/row = SW128 atom)
constexpr int KCH = HIDDEN / TK;    // 32 chunks

constexpr int ST_A = TM * 128;          // 16384 B per A subtile (hi or lo)
constexpr int ST_B = TN * 128;          // 32768 B for B (hi only)
constexpr int STAGE_BYTES = 2 * ST_A + ST_B;       // 65536
constexpr int SMEM_TILES  = 1024;
constexpr int SMEM_TOTAL  = SMEM_TILES + 2 * STAGE_BYTES;  // 132096

// Feature gate: tcgen05 only exists on the 'a' virtual arch (never true in this
// harness — PTX target is compute_103 — but kept for robustness).
#if defined(__CUDA_ARCH_FEAT_SM103_ALL) || defined(__CUDA_ARCH_FEAT_SM100_ALL)
#define USE_TCGEN05 1
#else
#define USE_TCGEN05 0
#endif

// idesc for tcgen05.mma cta_group::1 kind::f16, fp16 x fp16 -> f32
// bits[4:5]=dtype F32, [7:9]=atype F16(0), [10:12]=btype F16(0), [17:22]=N>>3, [24:28]=M>>4
constexpr uint32_t IDESC =
    (1u << 4) | ((TN / 8) << 17) | ((TM / 16) << 24);

// ============================================================
// Device scratch (no allocation allowed)
// ============================================================
__device__ float   g_resid[(size_t)TOKENS * HIDDEN];
__device__ __half  g_yhi  [(size_t)TOKENS * HIDDEN];
__device__ __half  g_ylo  [(size_t)TOKENS * HIDDEN];
__device__ __half  g_whT  [3][(size_t)HIDDEN * HIDDEN];   // W^T fp16

// ============================================================
// Helpers
// ============================================================
__device__ __forceinline__ uint32_t smem_u32(const void* p) {
    uint32_t a;
    asm("{ .reg .u64 t; cvta.to.shared.u64 t, %1; cvt.u32.u64 %0, t; }" : "=r"(a) : "l"(p));
    return a;
}

#define SW128(o) ((o) ^ (((o) >> 3) & 0x70))

#define CP_ASYNC16(dst, src) \
    asm volatile("cp.async.cg.shared.global [%0], [%1], 16;\n" :: "r"(dst), "l"(src))
#define CP_COMMIT() asm volatile("cp.async.commit_group;\n" ::: "memory")
#define CP_WAIT1()  asm volatile("cp.async.wait_group 1;\n" ::: "memory")
#define CP_WAIT0()  asm volatile("cp.async.wait_group 0;\n" ::: "memory")

#if USE_TCGEN05
__device__ __forceinline__ uint32_t elect_one() {
    uint32_t pred;
    asm volatile("{ .reg .pred p; elect.sync _|p, 0xFFFFFFFF; selp.b32 %0, 1, 0, p; }" : "=r"(pred));
    return pred;
}

#define MBARRIER_INIT(addr, cnt) \
    asm volatile("mbarrier.init.shared.b64 [%0], %1;" :: "r"((uint32_t)(addr)), "r"((uint32_t)(cnt)) : "memory")
#define MBARRIER_INVAL(addr) \
    asm volatile("mbarrier.inval.shared.b64 [%0];" :: "r"((uint32_t)(addr)) : "memory")

#define MBARRIER_WAIT_PARITY(mbar_smem_addr, phase_parity) do { \
    uint32_t _mbar = (uint32_t)(mbar_smem_addr); \
    uint32_t _parity = (uint32_t)(phase_parity); \
    uint32_t _done; \
    asm volatile( \
        "{\n\t.reg .pred p;\n\t" \
        "mbarrier.try_wait.parity.acquire.cta.shared::cta.b64 p, [%1], %2;\n\t" \
        "selp.b32 %0, 1, 0, p;\n\t}" \
        : "=r"(_done) : "r"(_mbar), "r"(_parity) : "memory"); \
    if (!_done) { \
        asm volatile( \
            "{\n\t.reg .pred P1;\n\t" \
            "WAIT_LOOP_%=:\n\t" \
            "mbarrier.try_wait.parity.acquire.cta.shared::cta.b64 P1, [%0], %1, 0x989680;\n\t" \
            "@P1 bra.uni WAIT_DONE_%=;\n\t" \
            "bra.uni WAIT_LOOP_%=;\n\t" \
            "WAIT_DONE_%=:\n\t}" \
            :: "r"(_mbar), "r"(_parity) : "memory"); \
    } \
} while(0)

#define TCGEN05_ALLOC(smem_result_addr, nCols) \
    asm volatile("tcgen05.alloc.cta_group::1.sync.aligned.shared::cta.b32 [%0], %1;" \
        :: "r"((uint32_t)(smem_result_addr)), "r"((uint32_t)(nCols)) : "memory")
#define TCGEN05_DEALLOC(tmem_addr, nCols) \
    asm volatile("tcgen05.dealloc.cta_group::1.sync.aligned.b32 %0, %1;" :: "r"(tmem_addr), "r"(nCols))
#define TCGEN05_RELINQUISH() \
    asm volatile("tcgen05.relinquish_alloc_permit.cta_group::1.sync.aligned;")
#define TCGEN05_COMMIT(mbar) \
    asm volatile("tcgen05.commit.cta_group::1.mbarrier::arrive::one.shared::cluster.b64 [%0];" \
        :: "r"((uint32_t)(mbar)) : "memory")
#define TCGEN05_WAIT_LD() asm volatile("tcgen05.wait::ld.sync.aligned;" ::: "memory")
#define TCGEN05_FENCE_BEFORE() asm volatile("tcgen05.fence::before_thread_sync;" ::: "memory")
#define TCGEN05_FENCE_AFTER()  asm volatile("tcgen05.fence::after_thread_sync;" ::: "memory")

#define TCGEN05_LD_32X32B_X32(r, tmem_addr) \
    asm volatile( \
        "tcgen05.ld.sync.aligned.32x32b.x32.b32 " \
        "{%0, %1, %2, %3, %4, %5, %6, %7, " \
        " %8, %9, %10, %11, %12, %13, %14, %15, " \
        " %16, %17, %18, %19, %20, %21, %22, %23, " \
        " %24, %25, %26, %27, %28, %29, %30, %31}, [%32];" \
        : "=r"((r)[0]),  "=r"((r)[1]),  "=r"((r)[2]),  "=r"((r)[3]), \
          "=r"((r)[4]),  "=r"((r)[5]),  "=r"((r)[6]),  "=r"((r)[7]), \
          "=r"((r)[8]),  "=r"((r)[9]),  "=r"((r)[10]), "=r"((r)[11]), \
          "=r"((r)[12]), "=r"((r)[13]), "=r"((r)[14]), "=r"((r)[15]), \
          "=r"((r)[16]), "=r"((r)[17]), "=r"((r)[18]), "=r"((r)[19]), \
          "=r"((r)[20]), "=r"((r)[21]), "=r"((r)[22]), "=r"((r)[23]), \
          "=r"((r)[24]), "=r"((r)[25]), "=r"((r)[26]), "=r"((r)[27]), \
          "=r"((r)[28]), "=r"((r)[29]), "=r"((r)[30]), "=r"((r)[31]) \
        : "r"(tmem_addr))

static constexpr uint64_t SMEM_DESC_BASE_SW128 =
    (uint64_t(2)  << 61) | (uint64_t(1) << 46) | (uint64_t(64) << 32) | (uint64_t(1) << 16);
#define MAKE_SMEM_DESC(base_addr) \
    (SMEM_DESC_BASE_SW128 | ((uint64_t)((base_addr) >> 4) & 0x3FFF))

__device__ __forceinline__ void mma_f16_ss(uint32_t d_tmem, uint64_t a_desc, uint64_t b_desc,
                                           uint32_t idesc, uint32_t enable) {
    asm volatile(
        "{\n\t.reg .pred p;\n\t"
        "setp.ne.u32 p, %5, 0;\n\t"
        "tcgen05.mma.cta_group::1.kind::f16 [%0], %1, %2, %3, {%4, %4, %4, %4}, p;\n\t}"
        :: "r"(d_tmem), "l"(a_desc), "l"(b_desc), "r"(idesc), "r"(0u), "r"(enable)
        : "memory");
}
#else
// ---- legacy mma.sync helpers (the path that actually compiles/runs) ----
__device__ __forceinline__ void ldsm_x4(uint32_t addr, uint32_t& r0, uint32_t& r1,
                                        uint32_t& r2, uint32_t& r3) {
    asm volatile("ldmatrix.sync.aligned.m8n8.x4.shared.b16 {%0,%1,%2,%3}, [%4];"
        : "=r"(r0), "=r"(r1), "=r"(r2), "=r"(r3) : "r"(addr));
}
__device__ __forceinline__ void ldsm_x2(uint32_t addr, uint32_t& r0, uint32_t& r1) {
    asm volatile("ldmatrix.sync.aligned.m8n8.x2.shared.b16 {%0,%1}, [%2];"
        : "=r"(r0), "=r"(r1) : "r"(addr));
}
__device__ __forceinline__ void mma16816(float& d0, float& d1, float& d2, float& d3,
                                         uint32_t a0, uint32_t a1, uint32_t a2, uint32_t a3,
                                         uint32_t b0, uint32_t b1) {
    asm volatile(
        "mma.sync.aligned.m16n8k16.row.col.f32.f16.f16.f32 "
        "{%0,%1,%2,%3}, {%4,%5,%6,%7}, {%8,%9}, {%0,%1,%2,%3};"
        : "+f"(d0), "+f"(d1), "+f"(d2), "+f"(d3)
        : "r"(a0), "r"(a1), "r"(a2), "r"(a3), "r"(b0), "r"(b1));
}
#endif

// ============================================================
// Weight prep: transpose + fp16 round.  W[k][n] -> WT[n][k]
// ============================================================
__global__ void prep_w(const float* __restrict__ W, int widx) {
    __shared__ float t[32][33];
    int x = blockIdx.x * 32 + threadIdx.x;   // n
    int y = blockIdx.y * 32 + threadIdx.y;   // k
    t[threadIdx.y][threadIdx.x] = W[(size_t)y * HIDDEN + x];
    __syncthreads();
    int n = blockIdx.x * 32 + threadIdx.y;
    int k = blockIdx.y * 32 + threadIdx.x;
    g_whT[widx][(size_t)n * HIDDEN + k] = __float2half_rn(t[threadIdx.x][threadIdx.y]);
}

// ============================================================
// Fused (relu) + rmsnorm.  flags: bit0 = relu (reads `in`, writes resid),
// bit1 = write split fp16 hi/lo.  Else write fp32 outf.
// ============================================================
__global__ void __launch_bounds__(256) norm_kernel(const float* __restrict__ in,
                                                   const float* __restrict__ gain,
                                                   float* __restrict__ outf,
                                                   int flags) {
    int row = blockIdx.x;
    int tid = threadIdx.x;
    const float* src = in ? in : g_resid;
    const float4* inp = reinterpret_cast<const float4*>(src + (size_t)row * HIDDEN);
    float4 v0 = inp[tid];
    float4 v1 = inp[tid + 256];

    if (flags & 1) {
        v0.x = fmaxf(v0.x, 0.f); v0.y = fmaxf(v0.y, 0.f);
        v0.z = fmaxf(v0.z, 0.f); v0.w = fmaxf(v0.w, 0.f);
        v1.x = fmaxf(v1.x, 0.f); v1.y = fmaxf(v1.y, 0.f);
        v1.z = fmaxf(v1.z, 0.f); v1.w = fmaxf(v1.w, 0.f);
        float4* rr = reinterpret_cast<float4*>(g_resid + (size_t)row * HIDDEN);
        rr[tid] = v0;
        rr[tid + 256] = v1;
    }

    float ss = v0.x * v0.x + v0.y * v0.y + v0.z * v0.z + v0.w * v0.w
             + v1.x * v1.x + v1.y * v1.y + v1.z * v1.z + v1.w * v1.w;
#pragma unroll
    for (int o = 16; o; o >>= 1) ss += __shfl_xor_sync(0xFFFFFFFFu, ss, o);
    __shared__ float red[8];
    if ((tid & 31) == 0) red[tid >> 5] = ss;
    __syncthreads();
    float tot = 0.f;
#pragma unroll
    for (int i = 0; i < 8; i++) tot += red[i];
    float scale = rsqrtf(tot * (1.0f / HIDDEN) + EPSV);

    const float4* gp = reinterpret_cast<const float4*>(gain);
    float4 gv0 = gp[tid], gv1 = gp[tid + 256];
    float4 y0, y1;
    y0.x = v0.x * scale * gv0.x; y0.y = v0.y * scale * gv0.y;
    y0.z = v0.z * scale * gv0.z; y0.w = v0.w * scale * gv0.w;
    y1.x = v1.x * scale * gv1.x; y1.y = v1.y * scale * gv1.y;
    y1.z = v1.z * scale * gv1.z; y1.w = v1.w * scale * gv1.w;

    if (flags & 2) {
        float yv[8] = {y0.x, y0.y, y0.z, y0.w, y1.x, y1.y, y1.z, y1.w};
        __half h[8], l[8];
#pragma unroll
        for (int i = 0; i < 8; i++) {
            h[i] = __float2half_rn(yv[i]);
            l[i] = __float2half_rn(yv[i] - __half2float(h[i]));
        }
        uint2* hp = reinterpret_cast<uint2*>(g_yhi + (size_t)row * HIDDEN);
        uint2* lp = reinterpret_cast<uint2*>(g_ylo + (size_t)row * HIDDEN);
        uint2 ph0, ph1, pl0, pl1;
        __half2 t;
        t = __half2(h[0], h[1]); ph0.x = *reinterpret_cast<uint32_t*>(&t);
        t = __half2(h[2], h[3]); ph0.y = *reinterpret_cast<uint32_t*>(&t);
        t = __half2(h[4], h[5]); ph1.x = *reinterpret_cast<uint32_t*>(&t);
        t = __half2(h[6], h[7]); ph1.y = *reinterpret_cast<uint32_t*>(&t);
        t = __half2(l[0], l[1]); pl0.x = *reinterpret_cast<uint32_t*>(&t);
        t = __half2(l[2], l[3]); pl0.y = *reinterpret_cast<uint32_t*>(&t);
        t = __half2(l[4], l[5]); pl1.x = *reinterpret_cast<uint32_t*>(&t);
        t = __half2(l[6], l[7]); pl1.y = *reinterpret_cast<uint32_t*>(&t);
        hp[tid] = ph0; hp[tid + 256] = ph1;
        lp[tid] = pl0; lp[tid + 256] = pl1;
    } else {
        float4* op = reinterpret_cast<float4*>(outf + (size_t)row * HIDDEN);
        op[tid] = y0;
        op[tid + 256] = y1;
    }
}

// ============================================================
// Loader: one K chunk (A hi, A lo, B hi) into SW128 SMEM stage. 256 threads.
// ============================================================
__device__ __forceinline__ void load_chunk(uint32_t sbase, int m0, int n0, int k0,
                                           const char* Bh, int tid) {
    const char* Ah = reinterpret_cast<const char*>(g_yhi);
    const char* Al = reinterpret_cast<const char*>(g_ylo);
    // A: 2 tensors x 128 rows x 8 x 16B = 2048 transfers
#pragma unroll
    for (int i = tid; i < 2048; i += 256) {
        int t = i >> 10; int rem = i & 1023; int r = rem >> 3; int cb = (rem & 7) * 16;
        uint32_t dst = sbase + t * ST_A + SW128(r * 128 + cb);
        const char* src = (t ? Al : Ah) + ((size_t)(m0 + r) * HIDDEN + k0) * 2 + cb;
        CP_ASYNC16(dst, src);
    }
    // B hi: 256 rows x 8 x 16B = 2048 transfers
#pragma unroll
    for (int i = tid; i < 2048; i += 256) {
        int r = i >> 3; int cb = (i & 7) * 16;
        uint32_t dst = sbase + 2 * ST_A + SW128(r * 128 + cb);
        const char* src = Bh + ((size_t)(n0 + r) * HIDDEN + k0) * 2 + cb;
        CP_ASYNC16(dst, src);
    }
}

// ============================================================
// GEMM: resid[m,n] += sum_k y[m,k] * W[k,n]  (split fp16 x2)
// ============================================================
__global__ void __launch_bounds__(256, 1) __cluster_dims__(1, 1, 1)
gemm_kernel(int widx) {
    extern __shared__ char smem[];
    uint32_t sb = smem_u32(smem);
    int tid = threadIdx.x, wid = tid >> 5, lid = tid & 31;
    int n0 = blockIdx.x * TN;
    int m0 = blockIdx.y * TM;
    const char* Bhg = reinterpret_cast<const char*>(g_whT[widx]);

    const uint32_t stage_base[2] = { sb + SMEM_TILES, sb + SMEM_TILES + STAGE_BYTES };

#if USE_TCGEN05
    // ---------------- tcgen05 path (inactive in this harness) ----------------
    if (wid == 0) TCGEN05_ALLOC(sb + 0, 256);
    if (tid == 0) {
        MBARRIER_INIT(sb + 16, 1);
        MBARRIER_INIT(sb + 24, 1);
        MBARRIER_INIT(sb + 32, 1);
    }
    __syncthreads();
    uint32_t tbase;
    asm volatile("ld.shared.b32 %0, [%1];" : "=r"(tbase) : "r"(sb + 0));

    load_chunk(stage_base[0], m0, n0, 0, Bhg, tid);
    CP_COMMIT();

    for (int c = 0; c < KCH; ++c) {
        int s = c & 1;
        if (c + 1 < KCH) {
            if (c >= 1) MBARRIER_WAIT_PARITY(sb + 16 + 8 * ((c - 1) & 1), ((c - 1) >> 1) & 1);
            load_chunk(stage_base[(c + 1) & 1], m0, n0, (c + 1) * TK, Bhg, tid);
            CP_COMMIT();
            CP_WAIT1();
        } else {
            CP_WAIT0();
        }
        asm volatile("fence.proxy.async.shared::cta;" ::: "memory");
        __syncthreads();

        if (wid == 0 && elect_one()) {
            uint64_t ah = MAKE_SMEM_DESC(stage_base[s]);
            uint64_t al = MAKE_SMEM_DESC(stage_base[s] + ST_A);
            uint64_t bh = MAKE_SMEM_DESC(stage_base[s] + 2 * ST_A);
#pragma unroll
            for (int ks = 0; ks < 4; ++ks) {
                mma_f16_ss(tbase, ah + ks * 2, bh + ks * 2, IDESC, (c != 0 || ks != 0));
                mma_f16_ss(tbase, al + ks * 2, bh + ks * 2, IDESC, 1u);
            }
            if (c == KCH - 1) TCGEN05_COMMIT(sb + 32);
            else              TCGEN05_COMMIT(sb + 16 + 8 * s);
        }
    }

    MBARRIER_WAIT_PARITY(sb + 32, 0);
    TCGEN05_FENCE_AFTER();

    {
        int row = (wid & 3) * 32 + lid;
        float* rp = g_resid + (size_t)(m0 + row) * HIDDEN + n0;
#pragma unroll
        for (int g = 0; g < 4; ++g) {
            int gcol = (wid >> 2) * 4 + g;
            uint32_t d[32];
            TCGEN05_LD_32X32B_X32(d, tbase + gcol * 32);
            TCGEN05_WAIT_LD();
#pragma unroll
            for (int j = 0; j < 32; j += 4) {
                float4 r4 = *reinterpret_cast<float4*>(rp + gcol * 32 + j);
                r4.x += __uint_as_float(d[j + 0]);
                r4.y += __uint_as_float(d[j + 1]);
                r4.z += __uint_as_float(d[j + 2]);
                r4.w += __uint_as_float(d[j + 3]);
                *reinterpret_cast<float4*>(rp + gcol * 32 + j) = r4;
            }
        }
    }
    TCGEN05_FENCE_BEFORE();
    __syncthreads();
    if (tid == 0) { MBARRIER_INVAL(sb + 16); MBARRIER_INVAL(sb + 24); MBARRIER_INVAL(sb + 32); }
    if (wid == 0) { TCGEN05_RELINQUISH(); TCGEN05_DEALLOC(tbase, 256); }

#else
    // ---------------- legacy mma.sync path ----------------
    // 8 warps, warp grid 2(m) x 4(n); warp tile 64x64.
    int wm = wid & 1;
    int wn = wid >> 1;
    int wm0 = wm * 64;
    int wn0 = wn * 64;

    float acc[4][8][4];
#pragma unroll
    for (int i = 0; i < 4; i++)
#pragma unroll
        for (int j = 0; j < 8; j++)
#pragma unroll
            for (int q = 0; q < 4; q++) acc[i][j][q] = 0.f;

    load_chunk(stage_base[0], m0, n0, 0, Bhg, tid);
    CP_COMMIT();

    for (int c = 0; c < KCH; ++c) {
        int s = c & 1;
        if (c + 1 < KCH) {
            load_chunk(stage_base[(c + 1) & 1], m0, n0, (c + 1) * TK, Bhg, tid);
            CP_COMMIT();
            CP_WAIT1();
        } else {
            CP_WAIT0();
        }
        __syncthreads();

        uint32_t aBaseH = stage_base[s];
        uint32_t aBaseL = stage_base[s] + ST_A;
        uint32_t bBaseH = stage_base[s] + 2 * ST_A;

#pragma unroll
        for (int ks = 0; ks < 4; ++ks) {
            int kbyte = ks * 32;   // 16 fp16 per k-step
            uint32_t ah[4][4], al[4][4];
#pragma unroll
            for (int mt = 0; mt < 4; ++mt) {
                int r = wm0 + mt * 16 + (lid & 15);
                int cb = kbyte + ((lid >> 4) << 4);
                uint32_t off = SW128(r * 128 + cb);
                ldsm_x4(aBaseH + off, ah[mt][0], ah[mt][1], ah[mt][2], ah[mt][3]);
                ldsm_x4(aBaseL + off, al[mt][0], al[mt][1], al[mt][2], al[mt][3]);
            }
#pragma unroll
            for (int nt = 0; nt < 8; ++nt) {
                int r = wn0 + nt * 8 + (lid & 7);
                int cb = kbyte + (((lid >> 3) & 1) << 4);
                uint32_t off = SW128(r * 128 + cb);
                uint32_t bh0, bh1;
                ldsm_x2(bBaseH + off, bh0, bh1);
#pragma unroll
                for (int mt = 0; mt < 4; ++mt) {
                    mma16816(acc[mt][nt][0], acc[mt][nt][1], acc[mt][nt][2], acc[mt][nt][3],
                             ah[mt][0], ah[mt][1], ah[mt][2], ah[mt][3], bh0, bh1);
                    mma16816(acc[mt][nt][0], acc[mt][nt][1], acc[mt][nt][2], acc[mt][nt][3],
                             al[mt][0], al[mt][1], al[mt][2], al[mt][3], bh0, bh1);
                }
            }
        }
        __syncthreads();
    }

    // epilogue: resid += acc
    {
        int qrow = lid >> 2;
        int qcol = (lid & 3) * 2;
#pragma unroll
        for (int mt = 0; mt < 4; ++mt) {
#pragma unroll
            for (int nt = 0; nt < 8; ++nt) {
                int grow = m0 + wm0 + mt * 16 + qrow;
                int gcol = n0 + wn0 + nt * 8 + qcol;
                float* p0 = g_resid + (size_t)grow * HIDDEN + gcol;
                float2 v0 = *reinterpret_cast<float2*>(p0);
                v0.x += acc[mt][nt][0]; v0.y += acc[mt][nt][1];
                *reinterpret_cast<float2*>(p0) = v0;
                float* p1 = g_resid + (size_t)(grow + 8) * HIDDEN + gcol;
                float2 v1 = *reinterpret_cast<float2*>(p1);
                v1.x += acc[mt][nt][2]; v1.y += acc[mt][nt][3];
                *reinterpret_cast<float2*>(p1) = v1;
            }
        }
    }
#endif
}

// ============================================================
// kernel_launch
// ============================================================
extern "C" void kernel_launch(void* const* d_in, const int* in_sizes, int n_in,
                              void* d_out, int out_size) {
    const float* x  = (const float*)d_in[0];
    const float* g0 = (const float*)d_in[1];
    const float* g1 = (const float*)d_in[2];
    const float* g2 = (const float*)d_in[3];
    const float* g3 = (const float*)d_in[4];
    const float* W[3] = { (const float*)d_in[5], (const float*)d_in[6], (const float*)d_in[7] };
    const float* gains[3] = { g1, g2, g3 };
    float* out = (float*)d_out;

    cudaFuncSetAttribute(gemm_kernel, cudaFuncAttributeMaxDynamicSharedMemorySize, SMEM_TOTAL);

    dim3 pb(32, 32), pg(HIDDEN / 32, HIDDEN / 32);
    for (int i = 0; i < 3; i++) prep_w<<<pg, pb>>>(W[i], i);

    norm_kernel<<<TOKENS, 256>>>(x, g0, nullptr, /*relu|split*/ 3);

    dim3 gg(HIDDEN / TN, TOKENS / TM);  // (8, 256)
    for (int s = 0; s < 3; s++) {
        gemm_kernel<<<gg, 256, SMEM_TOTAL>>>(s);
        if (s < 2) {
            norm_kernel<<<TOKENS, 256>>>(nullptr, gains[s], nullptr, /*split*/ 2);
        } else {
            norm_kernel<<<TOKENS, 256>>>(nullptr, gains[s], out, /*fp32 out*/ 0);
        }
    }
}